// round 6
// baseline (speedup 1.0000x reference)
#include <cuda_runtime.h>
#include <cuda_fp16.h>
#include <cstdint>

// out[65536,64] = xa[65536,256]@wa[256,64] + xb[65536,256]@wb[256,64]
// fp16 two-term scheme: A split (xh + xl, both fp16, exact to ~2^-22),
// B single fp16. mma.sync.m16n8k16.f32.f16.f16.f32.
// B pre-packed in fragment order (64 KB) -> smem verbatim copy.
// Register-dieted for 3 CTAs/SM (24 warps): per-ks 4-slot ping-pong prefetch.
// CTA: 128 rows x 64 cols, 256 threads, K=512 as 32 ks-groups of 16.

#define M_TILE 128
#define NSTEP  32          // 32 k-steps of 16

// fragment-packed B: index (t*8+ni)*32+L -> uint2 {b0,b1}, t = k-step 0..31
//   b0 = wh{k0,k0+1}, b1 = wh{k0+8,k0+9}; k0 = t*16+(L&3)*2, n = ni*8+(L>>2)
__device__ __align__(16) uint2 g_wfrag[NSTEP * 8 * 32];   // 64 KB

__device__ __forceinline__ uint32_t h2pack(float lo, float hi) {
    uint32_t r;
    asm("cvt.rn.f16x2.f32 %0, %1, %2;" : "=r"(r) : "f"(hi), "f"(lo));
    return r;
}

__device__ __forceinline__ void h2unpack(uint32_t p, float& lo, float& hi) {
    asm("{ .reg .b16 l, h; mov.b32 {l, h}, %2;\n\t"
        "cvt.f32.f16 %0, l; cvt.f32.f16 %1, h; }"
        : "=f"(lo), "=f"(hi) : "r"(p));
}

__device__ __forceinline__ void split2h(float x0, float x1,
                                        uint32_t& hp, uint32_t& lp) {
    hp = h2pack(x0, x1);
    float h0, h1;
    h2unpack(hp, h0, h1);
    lp = h2pack(x0 - h0, x1 - h1);
}

__device__ __forceinline__ void mma16816(float* c, const uint32_t* a,
                                         uint32_t b0, uint32_t b1) {
    asm volatile(
        "mma.sync.aligned.m16n8k16.row.col.f32.f16.f16.f32 "
        "{%0,%1,%2,%3}, {%4,%5,%6,%7}, {%8,%9}, {%0,%1,%2,%3};"
        : "+f"(c[0]), "+f"(c[1]), "+f"(c[2]), "+f"(c[3])
        : "r"(a[0]), "r"(a[1]), "r"(a[2]), "r"(a[3]), "r"(b0), "r"(b1));
}

// ---- pre-kernel: pack fp16(w) into fragment order ----
__global__ void wconv_kernel(const float* __restrict__ wa,
                             const float* __restrict__ wb) {
    int id = blockIdx.x * 256 + threadIdx.x;   // 0..8191
    int L  = id & 31;
    int ni = (id >> 5) & 7;
    int t  = id >> 8;                          // k-step 0..31
    int k0 = t * 16 + (L & 3) * 2;             // global k
    int n  = ni * 8 + (L >> 2);
    const float* __restrict__ w = (k0 < 256) ? wa : wb;
    int kk = k0 & 255;
    float v0 = w[kk * 64 + n];
    float v1 = w[(kk + 1) * 64 + n];
    float v8 = w[(kk + 8) * 64 + n];
    float v9 = w[(kk + 9) * 64 + n];
    g_wfrag[id] = make_uint2(h2pack(v0, v1), h2pack(v8, v9));
}

// ---- main kernel ----
__global__ void __launch_bounds__(256, 3)
sshe_mma_kernel(const float* __restrict__ xa, const float* __restrict__ xb,
                float* __restrict__ out) {
    extern __shared__ uint2 sB[];   // 8192 entries, verbatim g_wfrag
    const int tid = threadIdx.x;
    const int L = tid & 31;
    const int wid = tid >> 5;

    // copy B fragments to smem (identity layout)
    {
        const uint4* src = (const uint4*)g_wfrag;
        uint4* dst = (uint4*)sB;
#pragma unroll
        for (int i = 0; i < 16; i++) dst[tid + i * 256] = src[tid + i * 256];
    }
    __syncthreads();

    const int row = blockIdx.x * M_TILE + wid * 16 + (L >> 2);
    const int kk2 = (L & 3) * 2;
    const size_t roff0 = (size_t)row * 256 + kk2;
    const size_t roff1 = (size_t)(row + 8) * 256 + kk2;

    float acc[8][4];
#pragma unroll
    for (int i = 0; i < 8; i++)
#pragma unroll
        for (int j = 0; j < 4; j++) acc[i][j] = 0.f;

    // load the 4 fragment float2s for k-step t (t = 0..31, 16 k each)
    auto load_step = [&](int t, float2* d) {
        const float* __restrict__ xsrc = (t < 16) ? xa : xb;
        const int kb = (t & 15) * 16;
        d[0] = *(const float2*)(xsrc + roff0 + kb);
        d[1] = *(const float2*)(xsrc + roff1 + kb);
        d[2] = *(const float2*)(xsrc + roff0 + kb + 8);
        d[3] = *(const float2*)(xsrc + roff1 + kb + 8);
    };

    float2 buf0[4], buf1[4];
    load_step(0, buf0);

#pragma unroll 4
    for (int t = 0; t < NSTEP; t++) {
        float2* cur = (t & 1) ? buf1 : buf0;
        float2* nxt = (t & 1) ? buf0 : buf1;
        if (t + 1 < NSTEP) load_step(t + 1, nxt);

        uint32_t ah[4], al[4];
        split2h(cur[0].x, cur[0].y, ah[0], al[0]);
        split2h(cur[1].x, cur[1].y, ah[1], al[1]);
        split2h(cur[2].x, cur[2].y, ah[2], al[2]);
        split2h(cur[3].x, cur[3].y, ah[3], al[3]);

        const int base = t * 256 + L;
#pragma unroll
        for (int ni = 0; ni < 8; ni++) {
            uint2 B = sB[base + ni * 32];
            mma16816(acc[ni], ah, B.x, B.y);   // xh * wh
            mma16816(acc[ni], al, B.x, B.y);   // xl * wh
        }
    }

    // epilogue: c0,c1 -> (row, ni*8+kk2+{0,1}); c2,c3 -> (row+8, ...)
#pragma unroll
    for (int ni = 0; ni < 8; ni++) {
        float* o0 = out + (size_t)row * 64 + ni * 8 + kk2;
        float* o1 = out + (size_t)(row + 8) * 64 + ni * 8 + kk2;
        *(float2*)o0 = make_float2(acc[ni][0], acc[ni][1]);
        *(float2*)o1 = make_float2(acc[ni][2], acc[ni][3]);
    }
}

extern "C" void kernel_launch(void* const* d_in, const int* in_sizes, int n_in,
                              void* d_out, int out_size) {
    const float* xa = (const float*)d_in[0];
    const float* xb = (const float*)d_in[1];
    const float* wa = (const float*)d_in[2];
    const float* wb = (const float*)d_in[3];
    float* out = (float*)d_out;

    cudaFuncSetAttribute(sshe_mma_kernel,
                         cudaFuncAttributeMaxDynamicSharedMemorySize, 65536);

    wconv_kernel<<<32, 256>>>(wa, wb);

    const int batch = in_sizes[0] / 256;     // 65536
    sshe_mma_kernel<<<batch / M_TILE, 256, 65536>>>(xa, xb, out);
}

// round 7
// speedup vs baseline: 1.3336x; 1.3336x over previous
#include <cuda_runtime.h>
#include <cuda_fp16.h>
#include <cstdint>

// out[65536,64] = xa[65536,256]@wa[256,64] + xb[65536,256]@wb[256,64]
// fp16 two-term scheme: A split (xh + xl, both fp16, exact to ~2^-22),
// B single fp16. mma.sync.m16n8k16.f32.f16.f16.f32. rel_err ~2e-4.
// A staged global->smem via cp.async.cg (coalesced), double-buffered;
// fragments via LDS.64. B pre-packed in fragment order (64 KB smem).
// CTA: 128 rows x 64 cols, 256 threads, 2 CTAs/SM. K=512 in 16 chunks of 32.

#define M_TILE  128
#define NCHUNK  16
#define ASTRIDE 36                      // floats per smem A row (16B-aligned pad)
#define ASTAGE  (128 * ASTRIDE)         // 4608 floats = 18432 B
#define B_OFF   (2 * ASTAGE)            // B image starts after 2 A stages
#define SMEM_BYTES (2 * ASTAGE * 4 + 65536)   // 36864 + 65536 = 102400

// fragment-packed B: index (t*8+ni)*32+L -> uint2 {b0,b1}, t = k-step 0..31
//   b0 = wh{k0,k0+1}, b1 = wh{k0+8,k0+9}; k0 = t*16+(L&3)*2, n = ni*8+(L>>2)
__device__ __align__(16) uint2 g_wfrag[32 * 8 * 32];   // 64 KB

__device__ __forceinline__ uint32_t h2pack(float lo, float hi) {
    uint32_t r;
    asm("cvt.rn.f16x2.f32 %0, %1, %2;" : "=r"(r) : "f"(hi), "f"(lo));
    return r;
}

__device__ __forceinline__ void h2unpack(uint32_t p, float& lo, float& hi) {
    asm("{ .reg .b16 l, h; mov.b32 {l, h}, %2;\n\t"
        "cvt.f32.f16 %0, l; cvt.f32.f16 %1, h; }"
        : "=f"(lo), "=f"(hi) : "r"(p));
}

__device__ __forceinline__ void split2h(float x0, float x1,
                                        uint32_t& hp, uint32_t& lp) {
    hp = h2pack(x0, x1);
    float h0, h1;
    h2unpack(hp, h0, h1);
    lp = h2pack(x0 - h0, x1 - h1);
}

__device__ __forceinline__ void mma16816(float* c, const uint32_t* a,
                                         uint32_t b0, uint32_t b1) {
    asm volatile(
        "mma.sync.aligned.m16n8k16.row.col.f32.f16.f16.f32 "
        "{%0,%1,%2,%3}, {%4,%5,%6,%7}, {%8,%9}, {%0,%1,%2,%3};"
        : "+f"(c[0]), "+f"(c[1]), "+f"(c[2]), "+f"(c[3])
        : "r"(a[0]), "r"(a[1]), "r"(a[2]), "r"(a[3]), "r"(b0), "r"(b1));
}

__device__ __forceinline__ uint32_t smem_u32(const void* p) {
    uint32_t a;
    asm("{ .reg .u64 t; cvta.to.shared.u64 t, %1; cvt.u32.u64 %0, t; }"
        : "=r"(a) : "l"(p));
    return a;
}

// ---- pre-kernel: pack fp16(w) into fragment order ----
__global__ void wconv_kernel(const float* __restrict__ wa,
                             const float* __restrict__ wb) {
    int id = blockIdx.x * 256 + threadIdx.x;   // 0..8191
    int L  = id & 31;
    int ni = (id >> 5) & 7;
    int t  = id >> 8;                          // k-step 0..31
    int k0 = t * 16 + (L & 3) * 2;             // global k
    int n  = ni * 8 + (L >> 2);
    const float* __restrict__ w = (k0 < 256) ? wa : wb;
    int kk = k0 & 255;
    float v0 = w[kk * 64 + n];
    float v1 = w[(kk + 1) * 64 + n];
    float v8 = w[(kk + 8) * 64 + n];
    float v9 = w[(kk + 9) * 64 + n];
    g_wfrag[id] = make_uint2(h2pack(v0, v1), h2pack(v8, v9));
}

// ---- main kernel ----
__global__ void __launch_bounds__(256, 2)
sshe_mma_kernel(const float* __restrict__ xa, const float* __restrict__ xb,
                float* __restrict__ out) {
    extern __shared__ float sA[];                 // [2 stages A][B image]
    uint2* sB = (uint2*)(sA + B_OFF);
    const uint32_t sA_u = smem_u32(sA);
    const int tid = threadIdx.x;
    const int L = tid & 31;
    const int wid = tid >> 5;

    // copy B fragments to smem (identity layout)
    {
        const uint4* src = (const uint4*)g_wfrag;
        uint4* dst = (uint4*)sB;
#pragma unroll
        for (int i = 0; i < 16; i++) dst[tid + i * 256] = src[tid + i * 256];
    }

    // per-thread cp.async coordinates: 4 x 16B per stage
    const int ld_row = tid >> 3;          // rows tid>>3 + i*32
    const int ld_k4 = (tid & 7) * 4;      // float offset within 32-float chunk
    const long long row0 = (long long)blockIdx.x * M_TILE;

    auto issue_chunk = [&](int c, int s) {
        const float* __restrict__ xsrc = (c < 8) ? xa : xb;
        const size_t gbase = (size_t)(row0 + ld_row) * 256 + (c & 7) * 32 + ld_k4;
        uint32_t dbase = sA_u + (uint32_t)(s * ASTAGE + ld_row * ASTRIDE + ld_k4) * 4;
#pragma unroll
        for (int i = 0; i < 4; i++) {
            asm volatile("cp.async.cg.shared.global [%0], [%1], 16;"
                         :: "r"(dbase + (uint32_t)(i * 32 * ASTRIDE * 4)),
                            "l"(xsrc + gbase + (size_t)i * 32 * 256) : "memory");
        }
        asm volatile("cp.async.commit_group;" ::: "memory");
    };

    // fragment coordinates (identical to proven round-5 mapping)
    const int frow = wid * 16 + (L >> 2);          // local row of a0/a2
    const int kk2 = (L & 3) * 2;

    float acc[8][4];
#pragma unroll
    for (int i = 0; i < 8; i++)
#pragma unroll
        for (int j = 0; j < 4; j++) acc[i][j] = 0.f;

    issue_chunk(0, 0);
    __syncthreads();   // B image visible (cp.async of chunk0 pending is fine)

    for (int c = 0; c < NCHUNK; c++) {
        const int s = c & 1;
        if (c + 1 < NCHUNK) {
            issue_chunk(c + 1, s ^ 1);
            asm volatile("cp.async.wait_group 1;" ::: "memory");
        } else {
            asm volatile("cp.async.wait_group 0;" ::: "memory");
        }
        __syncthreads();   // stage s data visible to all warps

        const float* A0 = sA + s * ASTAGE + frow * ASTRIDE + kk2;
        const float* A1 = A0 + 8 * ASTRIDE;
#pragma unroll
        for (int ks = 0; ks < 2; ks++) {
            const int kb = ks * 16;
            float2 d0 = *(const float2*)(A0 + kb);
            float2 d1 = *(const float2*)(A1 + kb);
            float2 d2 = *(const float2*)(A0 + kb + 8);
            float2 d3 = *(const float2*)(A1 + kb + 8);
            uint32_t ah[4], al[4];
            split2h(d0.x, d0.y, ah[0], al[0]);
            split2h(d1.x, d1.y, ah[1], al[1]);
            split2h(d2.x, d2.y, ah[2], al[2]);
            split2h(d3.x, d3.y, ah[3], al[3]);
            const int base = (c * 2 + ks) * 256 + L;
#pragma unroll
            for (int ni = 0; ni < 8; ni++) {
                uint2 B = sB[base + ni * 32];
                mma16816(acc[ni], ah, B.x, B.y);   // xh * wh
                mma16816(acc[ni], al, B.x, B.y);   // xl * wh
            }
        }
        __syncthreads();   // stage s consumed; safe to overwrite next iter
    }

    // epilogue (proven): c0,c1 -> (row, ni*8+kk2+{0,1}); c2,c3 -> (row+8, ..)
    const size_t grow = row0 + frow;
#pragma unroll
    for (int ni = 0; ni < 8; ni++) {
        float* o0 = out + grow * 64 + ni * 8 + kk2;
        float* o1 = out + (grow + 8) * 64 + ni * 8 + kk2;
        *(float2*)o0 = make_float2(acc[ni][0], acc[ni][1]);
        *(float2*)o1 = make_float2(acc[ni][2], acc[ni][3]);
    }
}

extern "C" void kernel_launch(void* const* d_in, const int* in_sizes, int n_in,
                              void* d_out, int out_size) {
    const float* xa = (const float*)d_in[0];
    const float* xb = (const float*)d_in[1];
    const float* wa = (const float*)d_in[2];
    const float* wb = (const float*)d_in[3];
    float* out = (float*)d_out;

    cudaFuncSetAttribute(sshe_mma_kernel,
                         cudaFuncAttributeMaxDynamicSharedMemorySize,
                         SMEM_BYTES);

    wconv_kernel<<<32, 256>>>(wa, wb);

    const int batch = in_sizes[0] / 256;     // 65536
    sshe_mma_kernel<<<batch / M_TILE, 256, SMEM_BYTES>>>(xa, xb, out);
}

// round 8
// speedup vs baseline: 1.3354x; 1.0014x over previous
#include <cuda_runtime.h>
#include <cuda_fp16.h>
#include <cstdint>

// out[65536,64] = xa[65536,256]@wa[256,64] + xb[65536,256]@wb[256,64]
// fp16 two-term scheme: A split (xh + xl, both fp16), B single fp16.
// mma.sync.m16n8k16.f32.f16.f16.f32. rel_err ~2e-4.
// A: 4-stage cp.async ring (KC=16, 8KB/stage, XOR-swizzled, wait_group 2)
//    -> up to 3 chunks (24 KB/CTA) in flight, one syncthreads per chunk.
// B: pre-packed fragment image (64 KB) in smem.
// CTA: 128 rows x 64 cols, 256 threads, 2 CTAs/SM, grid 512.

#define M_TILE  128
#define NCHUNK  32                    // 32 chunks of 16 k
#define ASTAGE  2048                  // floats per stage: 128 rows * 16
#define NSTAGE  4
#define B_OFF   (NSTAGE * ASTAGE)     // float offset of B image
#define SMEM_BYTES (NSTAGE * ASTAGE * 4 + 65536)   // 32768 + 65536 = 98304

// fragment-packed B: index (t*8+ni)*32+L -> uint2 {b0,b1}, t = k-step 0..31
//   b0 = wh{k0,k0+1}, b1 = wh{k0+8,k0+9}; k0 = t*16+(L&3)*2, n = ni*8+(L>>2)
__device__ __align__(16) uint2 g_wfrag[32 * 8 * 32];   // 64 KB

__device__ __forceinline__ uint32_t h2pack(float lo, float hi) {
    uint32_t r;
    asm("cvt.rn.f16x2.f32 %0, %1, %2;" : "=r"(r) : "f"(hi), "f"(lo));
    return r;
}

__device__ __forceinline__ void h2unpack(uint32_t p, float& lo, float& hi) {
    asm("{ .reg .b16 l, h; mov.b32 {l, h}, %2;\n\t"
        "cvt.f32.f16 %0, l; cvt.f32.f16 %1, h; }"
        : "=f"(lo), "=f"(hi) : "r"(p));
}

__device__ __forceinline__ void split2h(float x0, float x1,
                                        uint32_t& hp, uint32_t& lp) {
    hp = h2pack(x0, x1);
    float h0, h1;
    h2unpack(hp, h0, h1);
    lp = h2pack(x0 - h0, x1 - h1);
}

__device__ __forceinline__ void mma16816(float* c, const uint32_t* a,
                                         uint32_t b0, uint32_t b1) {
    asm volatile(
        "mma.sync.aligned.m16n8k16.row.col.f32.f16.f16.f32 "
        "{%0,%1,%2,%3}, {%4,%5,%6,%7}, {%8,%9}, {%0,%1,%2,%3};"
        : "+f"(c[0]), "+f"(c[1]), "+f"(c[2]), "+f"(c[3])
        : "r"(a[0]), "r"(a[1]), "r"(a[2]), "r"(a[3]), "r"(b0), "r"(b1));
}

__device__ __forceinline__ uint32_t smem_u32(const void* p) {
    uint32_t a;
    asm("{ .reg .u64 t; cvta.to.shared.u64 t, %1; cvt.u32.u64 %0, t; }"
        : "=r"(a) : "l"(p));
    return a;
}

// ---- pre-kernel: pack fp16(w) into fragment order ----
__global__ void wconv_kernel(const float* __restrict__ wa,
                             const float* __restrict__ wb) {
    int id = blockIdx.x * 256 + threadIdx.x;   // 0..8191
    int L  = id & 31;
    int ni = (id >> 5) & 7;
    int t  = id >> 8;                          // k-step 0..31
    int k0 = t * 16 + (L & 3) * 2;             // global k
    int n  = ni * 8 + (L >> 2);
    const float* __restrict__ w = (k0 < 256) ? wa : wb;
    int kk = k0 & 255;
    float v0 = w[kk * 64 + n];
    float v1 = w[(kk + 1) * 64 + n];
    float v8 = w[(kk + 8) * 64 + n];
    float v9 = w[(kk + 9) * 64 + n];
    g_wfrag[id] = make_uint2(h2pack(v0, v1), h2pack(v8, v9));
}

// ---- main kernel ----
__global__ void __launch_bounds__(256, 2)
sshe_mma_kernel(const float* __restrict__ xa, const float* __restrict__ xb,
                float* __restrict__ out) {
    extern __shared__ float sA[];                 // [4 stages A][B image]
    uint2* sB = (uint2*)(sA + B_OFF);
    const uint32_t sA_u = smem_u32(sA);
    const int tid = threadIdx.x;
    const int L = tid & 31;
    const int wid = tid >> 5;

    // copy B fragments to smem (identity layout)
    {
        const uint4* src = (const uint4*)g_wfrag;
        uint4* dst = (uint4*)sB;
#pragma unroll
        for (int i = 0; i < 16; i++) dst[tid + i * 256] = src[tid + i * 256];
    }

    // cp.async coords: thread t -> row = t>>1, two 16B segs (t&1)*2+{0,1}
    const int ld_row = tid >> 1;
    const int ld_sg0 = (tid & 1) * 2;
    const int ld_xr = ld_row & 3;                 // seg XOR swizzle
    const long long row0 = (long long)blockIdx.x * M_TILE;

    auto issue_chunk = [&](int c, int s) {
        const float* __restrict__ xsrc = (c < 16) ? xa : xb;
        const float* g = xsrc + (size_t)(row0 + ld_row) * 256 + (c & 15) * 16 +
                         ld_sg0 * 4;
        uint32_t d = sA_u + (uint32_t)(s * ASTAGE + ld_row * 16) * 4;
        uint32_t d0 = d + (uint32_t)((ld_sg0 ^ ld_xr) << 4);
        uint32_t d1 = d + (uint32_t)(((ld_sg0 + 1) ^ ld_xr) << 4);
        asm volatile("cp.async.cg.shared.global [%0], [%1], 16;"
                     :: "r"(d0), "l"(g) : "memory");
        asm volatile("cp.async.cg.shared.global [%0], [%1], 16;"
                     :: "r"(d1), "l"(g + 4) : "memory");
    };

    // fragment coordinates (proven round-5 mapping)
    const int frow = wid * 16 + (L >> 2);
    const int kk2 = (L & 3) * 2;
    const int xr = (L >> 2) & 3;
    const int of = kk2 & 3;
    const int off_a0 = (((kk2 >> 2) ^ xr) << 2) + of;   // float offset in row
    const int off_a2 = off_a0 ^ 8;

    float acc[8][4];
#pragma unroll
    for (int i = 0; i < 8; i++)
#pragma unroll
        for (int j = 0; j < 4; j++) acc[i][j] = 0.f;

    // prologue: 3 stages in flight
#pragma unroll
    for (int c = 0; c < 3; c++) {
        issue_chunk(c, c);
        asm volatile("cp.async.commit_group;" ::: "memory");
    }

    for (int c = 0; c < NCHUNK; c++) {
        const int s = c & 3;
        asm volatile("cp.async.wait_group 2;" ::: "memory");
        __syncthreads();   // chunk c ready; all warps done with slot (c+3)&3

        if (c + 3 < NCHUNK) issue_chunk(c + 3, (c + 3) & 3);
        asm volatile("cp.async.commit_group;" ::: "memory");

        const float* A0 = sA + s * ASTAGE + frow * 16;
        const float* A1 = A0 + 128;     // +8 rows
        float2 d0 = *(const float2*)(A0 + off_a0);
        float2 d1 = *(const float2*)(A1 + off_a0);
        float2 d2 = *(const float2*)(A0 + off_a2);
        float2 d3 = *(const float2*)(A1 + off_a2);
        uint32_t ah[4], al[4];
        split2h(d0.x, d0.y, ah[0], al[0]);
        split2h(d1.x, d1.y, ah[1], al[1]);
        split2h(d2.x, d2.y, ah[2], al[2]);
        split2h(d3.x, d3.y, ah[3], al[3]);

        const int base = c * 256 + L;
#pragma unroll
        for (int ni = 0; ni < 8; ni++) {
            uint2 B = sB[base + ni * 32];
            mma16816(acc[ni], ah, B.x, B.y);   // xh * wh
            mma16816(acc[ni], al, B.x, B.y);   // xl * wh
        }
    }

    // epilogue (proven): c0,c1 -> (row, ni*8+kk2+{0,1}); c2,c3 -> (row+8, ..)
    const size_t grow = row0 + frow;
#pragma unroll
    for (int ni = 0; ni < 8; ni++) {
        float* o0 = out + grow * 64 + ni * 8 + kk2;
        float* o1 = out + (grow + 8) * 64 + ni * 8 + kk2;
        *(float2*)o0 = make_float2(acc[ni][0], acc[ni][1]);
        *(float2*)o1 = make_float2(acc[ni][2], acc[ni][3]);
    }
}

extern "C" void kernel_launch(void* const* d_in, const int* in_sizes, int n_in,
                              void* d_out, int out_size) {
    const float* xa = (const float*)d_in[0];
    const float* xb = (const float*)d_in[1];
    const float* wa = (const float*)d_in[2];
    const float* wb = (const float*)d_in[3];
    float* out = (float*)d_out;

    cudaFuncSetAttribute(sshe_mma_kernel,
                         cudaFuncAttributeMaxDynamicSharedMemorySize,
                         SMEM_BYTES);

    wconv_kernel<<<32, 256>>>(wa, wb);

    const int batch = in_sizes[0] / 256;     // 65536
    sshe_mma_kernel<<<batch / M_TILE, 256, SMEM_BYTES>>>(xa, xb, out);
}